// round 6
// baseline (speedup 1.0000x reference)
#include <cuda_runtime.h>
#include <cuda_bf16.h>
#include <cstdint>

// Problem shape (fixed by reference setup_inputs)
#define B_    16
#define C_    384
#define CR_   96
#define HW_   12544          // 112*112
#define HW4_  3136           // HW/4 (float4 per plane); 3136 = 448*7 exactly
#define T_    448
#define K_    7

// Scratch (no cudaMalloc allowed) — device globals.
__device__ float g_mean[B_ * C_];
__device__ float g_scale[B_ * C_];

// ---------------------------------------------------------------------------
// Kernel 1: per-plane mean for ONE batch (384 CTAs). Allocating loads leave
// x[b] resident in L2 for the scale kernel that follows on the other stream.
// ---------------------------------------------------------------------------
__global__ void __launch_bounds__(T_) se_reduce_kernel(const float* __restrict__ x,
                                                       int b) {
    const int plane = b * C_ + blockIdx.x;
    const float4* __restrict__ p =
        reinterpret_cast<const float4*>(x) + (size_t)plane * HW4_;

    float4 v[K_];
    #pragma unroll
    for (int k = 0; k < K_; k++)
        v[k] = p[threadIdx.x + k * T_];              // allocate in L2

    float sum = 0.0f;
    #pragma unroll
    for (int k = 0; k < K_; k++)
        sum += (v[k].x + v[k].y) + (v[k].z + v[k].w);

    #pragma unroll
    for (int o = 16; o > 0; o >>= 1)
        sum += __shfl_down_sync(0xffffffffu, sum, o);

    __shared__ float sdata[T_ / 32];
    const int lane = threadIdx.x & 31;
    const int wid  = threadIdx.x >> 5;
    if (lane == 0) sdata[wid] = sum;
    __syncthreads();
    if (wid == 0) {
        sum = (lane < (T_ / 32)) ? sdata[lane] : 0.0f;
        #pragma unroll
        for (int o = 8; o > 0; o >>= 1)
            sum += __shfl_down_sync(0xffffffffu, sum, o);
        if (lane == 0) g_mean[plane] = sum * (1.0f / (float)HW_);
    }
}

// ---------------------------------------------------------------------------
// Kernel 2: FC chain for ONE batch. 1 CTA x 384 threads. ~2us.
// ---------------------------------------------------------------------------
__global__ void __launch_bounds__(C_) se_fc_kernel(const float* __restrict__ w1,
                                                   const float* __restrict__ b1,
                                                   const float* __restrict__ w2,
                                                   const float* __restrict__ b2,
                                                   int b) {
    const int tid = threadIdx.x;

    __shared__ float s[C_];
    __shared__ float t[CR_];

    s[tid] = g_mean[b * C_ + tid];
    __syncthreads();

    if (tid < CR_) {
        float acc = b1[tid];
        const float* __restrict__ wr = w1 + tid * C_;
        #pragma unroll 8
        for (int c = 0; c < C_; c++) acc = fmaf(s[c], wr[c], acc);
        t[tid] = fmaxf(acc, 0.0f);
    }
    __syncthreads();

    float acc = b2[tid];
    const float* __restrict__ wc = w2 + tid * CR_;
    #pragma unroll 8
    for (int r = 0; r < CR_; r++) acc = fmaf(t[r], wc[r], acc);

    g_scale[b * C_ + tid] = __saturatef(fmaf(acc, 1.0f / 6.0f, 0.5f));
}

// ---------------------------------------------------------------------------
// Kernel 3: scale ONE batch (384 CTAs). Reads should hit L2 (x[b] was just
// pulled in by reduce); __ldcs evicts after the hit, __stcs streams writes.
// ---------------------------------------------------------------------------
__global__ void __launch_bounds__(T_) se_scale_kernel(const float* __restrict__ x,
                                                      float* __restrict__ out,
                                                      int b) {
    const int plane = b * C_ + blockIdx.x;
    const float sc = g_scale[plane];
    const float4* __restrict__ p =
        reinterpret_cast<const float4*>(x) + (size_t)plane * HW4_;
    float4* __restrict__ o =
        reinterpret_cast<float4*>(out) + (size_t)plane * HW4_;

    float4 v[K_];
    #pragma unroll
    for (int k = 0; k < K_; k++)
        v[k] = __ldcs(&p[threadIdx.x + k * T_]);

    #pragma unroll
    for (int k = 0; k < K_; k++) {
        v[k].x *= sc; v[k].y *= sc; v[k].z *= sc; v[k].w *= sc;
        __stcs(&o[threadIdx.x + k * T_], v[k]);
    }
}

// ---------------------------------------------------------------------------
// Two-stream pipeline:
//   stream 0 (harness/default): reduce(b); fc(b); record eF[b]
//   s1:                          wait eF[b); scale(b)
// join s1 back into stream 0 at the end. Pure stream-ordered DAG, graph-
// capturable (fork/join via events), no device memory allocation.
// ---------------------------------------------------------------------------
extern "C" void kernel_launch(void* const* d_in, const int* in_sizes, int n_in,
                              void* d_out, int out_size) {
    const float* x  = (const float*)d_in[0];
    const float* w1 = (const float*)d_in[1];
    const float* b1 = (const float*)d_in[2];
    const float* w2 = (const float*)d_in[3];
    const float* b2 = (const float*)d_in[4];
    float* out = (float*)d_out;

    // One-time resource init (streams/events are host resources, not device
    // memory; every call performs the identical launch sequence).
    static cudaStream_t s1 = nullptr;
    static cudaEvent_t  eF[B_];
    static cudaEvent_t  eJoin = nullptr;
    if (s1 == nullptr) {
        cudaStreamCreateWithFlags(&s1, cudaStreamNonBlocking);
        for (int i = 0; i < B_; i++)
            cudaEventCreateWithFlags(&eF[i], cudaEventDisableTiming);
        cudaEventCreateWithFlags(&eJoin, cudaEventDisableTiming);
    }

    for (int b = 0; b < B_; b++) {
        se_reduce_kernel<<<C_, T_, 0, 0>>>(x, b);
        se_fc_kernel<<<1, C_, 0, 0>>>(w1, b1, w2, b2, b);
        cudaEventRecord(eF[b], 0);
        cudaStreamWaitEvent(s1, eF[b], 0);
        se_scale_kernel<<<C_, T_, 0, s1>>>(x, out, b);
    }

    // Join the side stream back into the main (captured) stream.
    cudaEventRecord(eJoin, s1);
    cudaStreamWaitEvent(0, eJoin, 0);
}

// round 7
// speedup vs baseline: 2.5466x; 2.5466x over previous
#include <cuda_runtime.h>
#include <cuda_bf16.h>
#include <cstdint>

// Problem shape (fixed by reference setup_inputs)
#define B_    16
#define C_    384
#define CR_   96
#define HW_   12544          // 112*112
#define HW4_  3136           // HW/4 (float4 per plane); 3136 = 448*7 exactly
#define NPLANES_ (B_ * C_)   // 6144

#define T_    448            // threads per CTA
#define K_    7              // float4 per thread per plane
#define GRID_ 444            // 148 SMs * 3 CTAs/SM (co-residency guaranteed)
#define NW_   (T_ / 32)      // 14 warps
#define MAXJ_ 14             // max planes per CTA in phase C

// Device-global scratch & barrier state (no allocations allowed).
__device__ float    g_mean[NPLANES_];
__device__ unsigned g_bar_ctr;    // self-resetting arrival counter
__device__ unsigned g_bar_epoch;  // monotone release epoch (replay-safe)

__global__ void __launch_bounds__(T_, 3)
se_persistent_kernel(const float* __restrict__ x,
                     const float* __restrict__ w1, const float* __restrict__ b1,
                     const float* __restrict__ w2, const float* __restrict__ b2,
                     float* __restrict__ out)
{
    __shared__ float t_all[B_][CR_];   // 16 x 96 = 6KB
    __shared__ float s_sc[MAXJ_];
    __shared__ float s_warp[NW_];

    const int cta  = blockIdx.x;
    const int tid  = threadIdx.x;
    const int lane = tid & 31;
    const int wid  = tid >> 5;

    const float4* __restrict__ x4 = reinterpret_cast<const float4*>(x);
    float4*       __restrict__ o4 = reinterpret_cast<float4*>(out);

    // Snapshot barrier epoch BEFORE doing any work / arriving.
    unsigned epoch0 = 0u;
    if (tid == 0) epoch0 = *((volatile const unsigned*)&g_bar_epoch);

    // ---------------- Phase A: reduce (ascending planes) -----------------
    for (int p = cta; p < NPLANES_; p += GRID_) {
        const float4* __restrict__ pp = x4 + (size_t)p * HW4_;
        float4 v[K_];
        #pragma unroll
        for (int k = 0; k < K_; k++)
            v[k] = pp[tid + k * T_];               // allocating: warm L2

        float sum = 0.0f;
        #pragma unroll
        for (int k = 0; k < K_; k++)
            sum += (v[k].x + v[k].y) + (v[k].z + v[k].w);

        #pragma unroll
        for (int o = 16; o > 0; o >>= 1)
            sum += __shfl_down_sync(0xffffffffu, sum, o);
        if (lane == 0) s_warp[wid] = sum;
        __syncthreads();
        if (wid == 0) {
            sum = (lane < NW_) ? s_warp[lane] : 0.0f;
            #pragma unroll
            for (int o = 8; o > 0; o >>= 1)
                sum += __shfl_down_sync(0xffffffffu, sum, o);
            if (lane == 0) g_mean[p] = sum * (1.0f / (float)HW_);
        }
        __syncthreads();                            // s_warp reuse
    }

    // ---------------- Single grid barrier ---------------------------------
    if (tid == 0) {
        __threadfence();                            // means visible at L2
        unsigned old = atomicAdd(&g_bar_ctr, 1u);
        if (old == (unsigned)(GRID_ - 1)) {
            g_bar_ctr = 0;                          // reset for next replay
            __threadfence();
            atomicAdd(&g_bar_epoch, 1u);            // release
        } else {
            while (*((volatile const unsigned*)&g_bar_epoch) == epoch0)
                __nanosleep(64);
        }
        __threadfence();
    }
    __syncthreads();

    // ---------------- Phase B: redundant FC per CTA -----------------------
    // t_all[b][r] = relu(dot(w1[r,:], mean[b,:]) + b1[r]) for all 16 batches.
    // 1536 dots, one warp per dot, coalesced w1/mean reads (L1/L2-resident).
    for (int d = wid; d < B_ * CR_; d += NW_) {
        const int b = d / CR_;
        const int r = d % CR_;
        const float* __restrict__ wr = w1 + r * C_;
        const float* __restrict__ sb = g_mean + b * C_;
        float acc = 0.0f;
        #pragma unroll
        for (int k = 0; k < C_ / 32; k++) {
            const int c = lane + 32 * k;
            acc = fmaf(__ldg(&wr[c]), __ldcg(&sb[c]), acc);
        }
        #pragma unroll
        for (int o = 16; o > 0; o >>= 1)
            acc += __shfl_down_sync(0xffffffffu, acc, o);
        if (lane == 0) t_all[b][r] = fmaxf(acc + __ldg(&b1[r]), 0.0f);
    }
    __syncthreads();

    // Scale factors for this CTA's phase-C planes: p_j = 6143 - cta - 444*j.
    for (int j = wid; ; j += NW_) {
        const int p = (NPLANES_ - 1) - cta - GRID_ * j;
        if (p < 0) break;
        const int b = p / C_;
        const int c = p % C_;
        const float* __restrict__ wc = w2 + c * CR_;
        float acc = 0.0f;
        #pragma unroll
        for (int k = 0; k < CR_ / 32; k++) {
            const int r = lane + 32 * k;
            acc = fmaf(__ldg(&wc[r]), t_all[b][r], acc);
        }
        #pragma unroll
        for (int o = 16; o > 0; o >>= 1)
            acc += __shfl_down_sync(0xffffffffu, acc, o);
        if (lane == 0)
            s_sc[j] = __saturatef(fmaf(acc + __ldg(&b2[c]), 1.0f / 6.0f, 0.5f));
    }
    __syncthreads();

    // ---------------- Phase C: scale (descending planes: L2-hot first) ----
    for (int j = 0; ; j++) {
        const int p = (NPLANES_ - 1) - cta - GRID_ * j;
        if (p < 0) break;
        const float sc = s_sc[j];
        const float4* __restrict__ pp = x4 + (size_t)p * HW4_;
        float4*       __restrict__ po = o4 + (size_t)p * HW4_;

        float4 v[K_];
        #pragma unroll
        for (int k = 0; k < K_; k++)
            v[k] = __ldcs(&pp[tid + k * T_]);
        #pragma unroll
        for (int k = 0; k < K_; k++) {
            v[k].x *= sc; v[k].y *= sc; v[k].z *= sc; v[k].w *= sc;
            __stcs(&po[tid + k * T_], v[k]);
        }
    }
}

// ---------------------------------------------------------------------------
extern "C" void kernel_launch(void* const* d_in, const int* in_sizes, int n_in,
                              void* d_out, int out_size) {
    const float* x  = (const float*)d_in[0];
    const float* w1 = (const float*)d_in[1];
    const float* b1 = (const float*)d_in[2];
    const float* w2 = (const float*)d_in[3];
    const float* b2 = (const float*)d_in[4];
    float* out = (float*)d_out;

    se_persistent_kernel<<<GRID_, T_>>>(x, w1, b1, w2, b2, out);
}

// round 8
// speedup vs baseline: 3.3602x; 1.3195x over previous
#include <cuda_runtime.h>
#include <cuda_bf16.h>
#include <cstdint>

// Problem shape (fixed by reference setup_inputs)
#define B_    16
#define C_    384
#define CR_   96
#define HW_   12544          // 112*112
#define HW4_  3136           // HW/4 (float4 per plane); 3136 = 448*7 exactly
#define T_    448
#define K_    7

#define HALF_B_   8                      // batches per half
#define HPLANES_  (HALF_B_ * C_)         // 3072 CTAs per half kernel

// Scratch (no cudaMalloc allowed) — device globals.
__device__ float g_mean[B_ * C_];
__device__ float g_scale[B_ * C_];

// ---------------------------------------------------------------------------
// Kernel 1: per-plane mean for one 8-batch half. Allocating loads (warm L2).
// ---------------------------------------------------------------------------
__global__ void __launch_bounds__(T_) se_reduce_kernel(const float* __restrict__ x,
                                                       int b0) {
    const int plane = b0 * C_ + blockIdx.x;
    const float4* __restrict__ p =
        reinterpret_cast<const float4*>(x) + (size_t)plane * HW4_;

    float4 v[K_];
    #pragma unroll
    for (int k = 0; k < K_; k++)
        v[k] = p[threadIdx.x + k * T_];

    float sum = 0.0f;
    #pragma unroll
    for (int k = 0; k < K_; k++)
        sum += (v[k].x + v[k].y) + (v[k].z + v[k].w);

    #pragma unroll
    for (int o = 16; o > 0; o >>= 1)
        sum += __shfl_down_sync(0xffffffffu, sum, o);

    __shared__ float sdata[T_ / 32];
    const int lane = threadIdx.x & 31;
    const int wid  = threadIdx.x >> 5;
    if (lane == 0) sdata[wid] = sum;
    __syncthreads();
    if (wid == 0) {
        sum = (lane < (T_ / 32)) ? sdata[lane] : 0.0f;
        #pragma unroll
        for (int o = 8; o > 0; o >>= 1)
            sum += __shfl_down_sync(0xffffffffu, sum, o);
        if (lane == 0) g_mean[plane] = sum * (1.0f / (float)HW_);
    }
}

// ---------------------------------------------------------------------------
// Kernel 2: FC chain for one half (8 CTAs x 384 threads). ~2us.
// ---------------------------------------------------------------------------
__global__ void __launch_bounds__(C_) se_fc_kernel(const float* __restrict__ w1,
                                                   const float* __restrict__ b1,
                                                   const float* __restrict__ w2,
                                                   const float* __restrict__ b2,
                                                   int b0) {
    const int b   = b0 + blockIdx.x;
    const int tid = threadIdx.x;

    __shared__ float s[C_];
    __shared__ float t[CR_];

    s[tid] = g_mean[b * C_ + tid];
    __syncthreads();

    if (tid < CR_) {
        float acc = b1[tid];
        const float* __restrict__ wr = w1 + tid * C_;
        #pragma unroll 8
        for (int c = 0; c < C_; c++) acc = fmaf(s[c], wr[c], acc);
        t[tid] = fmaxf(acc, 0.0f);
    }
    __syncthreads();

    float acc = b2[tid];
    const float* __restrict__ wc = w2 + tid * CR_;
    #pragma unroll 8
    for (int r = 0; r < CR_; r++) acc = fmaf(t[r], wc[r], acc);

    g_scale[b * C_ + tid] = __saturatef(fmaf(acc, 1.0f / 6.0f, 0.5f));
}

// ---------------------------------------------------------------------------
// Kernel 3: scale one half, reverse plane order (L2-hot tail first).
// Streaming hints: reads are dead after use; writes shouldn't pollute L2
// while the concurrent reduce kernel is warming it.
// ---------------------------------------------------------------------------
__global__ void __launch_bounds__(T_) se_scale_kernel(const float* __restrict__ x,
                                                      float* __restrict__ out,
                                                      int b0) {
    const int plane = b0 * C_ + (HPLANES_ - 1 - blockIdx.x);
    const float sc = g_scale[plane];
    const float4* __restrict__ p =
        reinterpret_cast<const float4*>(x) + (size_t)plane * HW4_;
    float4* __restrict__ o =
        reinterpret_cast<float4*>(out) + (size_t)plane * HW4_;

    float4 v[K_];
    #pragma unroll
    for (int k = 0; k < K_; k++)
        v[k] = __ldcs(&p[threadIdx.x + k * T_]);

    #pragma unroll
    for (int k = 0; k < K_; k++) {
        v[k].x *= sc; v[k].y *= sc; v[k].z *= sc; v[k].w *= sc;
        __stcs(&o[threadIdx.x + k * T_], v[k]);
    }
}

// ---------------------------------------------------------------------------
// Two-stream overlapped schedule (6 kernel nodes):
//   main:  reduce(H0) fc(H0) [e1]  reduce(H1) fc(H1) [e2]
//   side:  wait e1  scale(H0)   wait e2  scale(H1)   [join]
// scale(H0) overlaps reduce(H1): pure-read + mixed streams share HBM.
// ---------------------------------------------------------------------------
extern "C" void kernel_launch(void* const* d_in, const int* in_sizes, int n_in,
                              void* d_out, int out_size) {
    const float* x  = (const float*)d_in[0];
    const float* w1 = (const float*)d_in[1];
    const float* b1 = (const float*)d_in[2];
    const float* w2 = (const float*)d_in[3];
    const float* b2 = (const float*)d_in[4];
    float* out = (float*)d_out;

    // One-time host resource init (no device memory involved).
    static cudaStream_t s1 = nullptr;
    static cudaEvent_t  e1 = nullptr, e2 = nullptr, eJoin = nullptr;
    if (s1 == nullptr) {
        cudaStreamCreateWithFlags(&s1, cudaStreamNonBlocking);
        cudaEventCreateWithFlags(&e1,    cudaEventDisableTiming);
        cudaEventCreateWithFlags(&e2,    cudaEventDisableTiming);
        cudaEventCreateWithFlags(&eJoin, cudaEventDisableTiming);
    }

    // Half 0 squeeze+fc on main stream.
    se_reduce_kernel<<<HPLANES_, T_, 0, 0>>>(x, 0);
    se_fc_kernel<<<HALF_B_, C_, 0, 0>>>(w1, b1, w2, b2, 0);
    cudaEventRecord(e1, 0);

    // Half 1 squeeze+fc on main stream (overlaps scale(H0) below).
    se_reduce_kernel<<<HPLANES_, T_, 0, 0>>>(x, HALF_B_);
    se_fc_kernel<<<HALF_B_, C_, 0, 0>>>(w1, b1, w2, b2, HALF_B_);
    cudaEventRecord(e2, 0);

    // Side stream: scale halves as their fc results land.
    cudaStreamWaitEvent(s1, e1, 0);
    se_scale_kernel<<<HPLANES_, T_, 0, s1>>>(x, out, 0);
    cudaStreamWaitEvent(s1, e2, 0);
    se_scale_kernel<<<HPLANES_, T_, 0, s1>>>(x, out, HALF_B_);

    // Join side stream back into the captured main stream.
    cudaEventRecord(eJoin, s1);
    cudaStreamWaitEvent(0, eJoin, 0);
}

// round 9
// speedup vs baseline: 4.7815x; 1.4230x over previous
#include <cuda_runtime.h>
#include <cuda_bf16.h>
#include <cstdint>

// Problem shape (fixed by reference setup_inputs)
#define B_    16
#define C_    384
#define CR_   96
#define HW_   12544          // 112*112
#define HW4_  3136           // HW/4 (float4 per plane); 3136 = 448*7 exactly
#define NPLANES_ (B_ * C_)   // 6144
#define T_    448
#define K_    7
#define FCW_  12             // warps in fc kernel (384 threads)

// Scratch (no cudaMalloc allowed) — device globals.
__device__ float g_mean[NPLANES_];
__device__ float g_scale[NPLANES_];

// ---------------------------------------------------------------------------
// Kernel 1: per-plane mean. One CTA per plane. At DRAM roofline (84%).
// ---------------------------------------------------------------------------
__global__ void __launch_bounds__(T_) se_reduce_kernel(const float* __restrict__ x) {
    const int plane = blockIdx.x;
    const float4* __restrict__ p =
        reinterpret_cast<const float4*>(x) + (size_t)plane * HW4_;

    float4 v[K_];
    #pragma unroll
    for (int k = 0; k < K_; k++)
        v[k] = p[threadIdx.x + k * T_];

    float sum = 0.0f;
    #pragma unroll
    for (int k = 0; k < K_; k++)
        sum += (v[k].x + v[k].y) + (v[k].z + v[k].w);

    #pragma unroll
    for (int o = 16; o > 0; o >>= 1)
        sum += __shfl_down_sync(0xffffffffu, sum, o);

    __shared__ float sdata[T_ / 32];
    const int lane = threadIdx.x & 31;
    const int wid  = threadIdx.x >> 5;
    if (lane == 0) sdata[wid] = sum;
    __syncthreads();
    if (wid == 0) {
        sum = (lane < (T_ / 32)) ? sdata[lane] : 0.0f;
        #pragma unroll
        for (int o = 8; o > 0; o >>= 1)
            sum += __shfl_down_sync(0xffffffffu, sum, o);
        if (lane == 0) g_mean[plane] = sum * (1.0f / (float)HW_);
    }
}

// ---------------------------------------------------------------------------
// Kernel 2: FC chain, warp-cooperative (FIXED: was 47us latency-bound).
// One CTA per batch, 12 warps. Every dot product is computed by a full warp
// with coalesced float4/scalar weight loads; 16 CTAs share weights via L2.
// ---------------------------------------------------------------------------
__global__ void __launch_bounds__(C_) se_fc_kernel(const float* __restrict__ w1,
                                                   const float* __restrict__ b1,
                                                   const float* __restrict__ w2,
                                                   const float* __restrict__ b2) {
    const int b    = blockIdx.x;
    const int tid  = threadIdx.x;
    const int lane = tid & 31;
    const int wid  = tid >> 5;

    __shared__ float s[C_];
    __shared__ float t[CR_];

    s[tid] = g_mean[b * C_ + tid];
    __syncthreads();

    // Phase 1: t[r] = relu(dot(w1[r,:], s) + b1[r]); warp per row, 8 rows/warp.
    for (int r = wid; r < CR_; r += FCW_) {
        const float4* __restrict__ wr4 =
            reinterpret_cast<const float4*>(w1 + r * C_);   // 96 float4
        float acc = 0.0f;
        #pragma unroll
        for (int k = 0; k < 3; k++) {
            const int i4 = lane + 32 * k;
            const float4 wv = __ldg(&wr4[i4]);
            const int c = i4 * 4;
            acc = fmaf(wv.x, s[c + 0], acc);
            acc = fmaf(wv.y, s[c + 1], acc);
            acc = fmaf(wv.z, s[c + 2], acc);
            acc = fmaf(wv.w, s[c + 3], acc);
        }
        #pragma unroll
        for (int o = 16; o > 0; o >>= 1)
            acc += __shfl_down_sync(0xffffffffu, acc, o);
        if (lane == 0) t[r] = fmaxf(acc + __ldg(&b1[r]), 0.0f);
    }
    __syncthreads();

    // Phase 2: out[c] = hardsigmoid(dot(w2[c,:], t) + b2[c]); warp per output,
    // 32 outputs/warp, coalesced scalar loads (96 = 3x32).
    for (int c = wid; c < C_; c += FCW_) {
        const float* __restrict__ wc = w2 + c * CR_;
        float acc = 0.0f;
        #pragma unroll
        for (int k = 0; k < 3; k++) {
            const int r = lane + 32 * k;
            acc = fmaf(__ldg(&wc[r]), t[r], acc);
        }
        #pragma unroll
        for (int o = 16; o > 0; o >>= 1)
            acc += __shfl_down_sync(0xffffffffu, acc, o);
        if (lane == 0)
            g_scale[b * C_ + c] =
                __saturatef(fmaf(acc + __ldg(&b2[c]), 1.0f / 6.0f, 0.5f));
    }
}

// ---------------------------------------------------------------------------
// Kernel 3: broadcast multiply. Reverse plane order (L2-hot tail first),
// streaming hints. Measured ~6.9 TB/s effective — at roofline.
// ---------------------------------------------------------------------------
__global__ void __launch_bounds__(T_) se_scale_kernel(const float* __restrict__ x,
                                                      float* __restrict__ out) {
    const int plane = (NPLANES_ - 1) - blockIdx.x;
    const float sc = g_scale[plane];
    const float4* __restrict__ p =
        reinterpret_cast<const float4*>(x) + (size_t)plane * HW4_;
    float4* __restrict__ o =
        reinterpret_cast<float4*>(out) + (size_t)plane * HW4_;

    float4 v[K_];
    #pragma unroll
    for (int k = 0; k < K_; k++)
        v[k] = __ldcs(&p[threadIdx.x + k * T_]);

    #pragma unroll
    for (int k = 0; k < K_; k++) {
        v[k].x *= sc; v[k].y *= sc; v[k].z *= sc; v[k].w *= sc;
        __stcs(&o[threadIdx.x + k * T_], v[k]);
    }
}

// ---------------------------------------------------------------------------
extern "C" void kernel_launch(void* const* d_in, const int* in_sizes, int n_in,
                              void* d_out, int out_size) {
    const float* x  = (const float*)d_in[0];
    const float* w1 = (const float*)d_in[1];
    const float* b1 = (const float*)d_in[2];
    const float* w2 = (const float*)d_in[3];
    const float* b2 = (const float*)d_in[4];
    float* out = (float*)d_out;

    se_reduce_kernel<<<NPLANES_, T_>>>(x);
    se_fc_kernel<<<B_, C_>>>(w1, b1, w2, b2);
    se_scale_kernel<<<NPLANES_, T_>>>(x, out);
}